// round 5
// baseline (speedup 1.0000x reference)
#include <cuda_runtime.h>

namespace {

constexpr int G  = 8;    // group size
constexpr int L  = 50;   // history length
constexpr int S  = 32;   // social neighbors
constexpr int D  = 64;   // embed dim
constexpr int A  = 16;   // attention dim
constexpr int NR = 5;    // num ratings
constexpr int R  = 4;    // batch rows per CTA
constexpr int NT = 256;  // threads per CTA

constexpr int BMAX = 16384;

// intermediate: [B][2*D] = [self | neigh]
__device__ float g_comb[BMAX * 2 * D];

__device__ __forceinline__ bool mask_at(const void* m, long idx, int kind)
{
    if (kind == 1) return ((const int*)m)[idx] != 0;
    if (kind == 2) return ((const float*)m)[idx] != 0.f;
    return ((const unsigned char*)m)[idx] != 0;
}

__device__ __forceinline__ float fast_tanh(float x)
{
    float y;
    asm("tanh.approx.f32 %0, %1;" : "=f"(y) : "f"(x));
    return y;
}

__global__ __launch_bounds__(NT, 6)
void enc_kernel(const int* __restrict__ nodes,
                const int* __restrict__ hist_u,
                const int* __restrict__ hist_r,
                const void* __restrict__ hist_m,
                const int* __restrict__ soc_a,
                const void* __restrict__ soc_m,
                const float* __restrict__ features,
                const float* __restrict__ r_embed,
                const float* __restrict__ wg1,
                const float* __restrict__ bg1,
                const float* __restrict__ wg2,
                const float* __restrict__ bg2)
{
    __shared__ __align__(16) float4 s_mem4[R][G][D / 4];   // member embeddings (8 KB)
    __shared__ __align__(16) float  s_wg1T[A][68];          // wg1 transposed, padded
    __shared__ __align__(16) float4 s_red[8][R][D / 4];     // gather partials (8 KB)
    __shared__ float s_lg[2][R][G];
    __shared__ int   s_hu[R][L];
    __shared__ int   s_su[R][S];
    __shared__ int   s_wcnt[R][2];        // hist per-warp counts
    __shared__ int   s_sn[R];
    __shared__ int   s_rcnt2[R][2][NR];   // per-warp rating histograms
    __shared__ int   s_flags[2];

    const int tid  = threadIdx.x;
    const int b0   = blockIdx.x * R;
    const int r    = tid >> 6;
    const int t    = tid & 63;
    const int lane = tid & 31;

    // ---------- P0 ----------
    if (tid < 2) s_flags[tid] = 0;
    __syncthreads();

    // ---------- P1: mask dtype detection + stage members + wg1T ----------
    if (tid < 64) {
        unsigned int v = ((const unsigned int*)hist_m)[tid];
        if (v > 1u)                      s_flags[0] = 1;   // benign race: only writes 1
        if (v != 0u && v != 0x3F800000u) s_flags[1] = 1;
    }
    for (int i = tid; i < R * G * (D / 4); i += NT) {
        int rr = i >> 7, g = (i >> 4) & 7, d4 = i & 15;
        int u = nodes[(b0 + rr) * G + g];
        s_mem4[rr][g][d4] = ((const float4*)features)[u * (D / 4) + d4];
    }
    for (int i = tid; i < D * A; i += NT) {
        int dd = i >> 4, a = i & 15;
        s_wg1T[a][dd] = wg1[i];
    }
    __syncthreads();

    const int kind = (!s_flags[0]) ? 1 : ((!s_flags[1]) ? 2 : 0);

    // ---------- P2a: ballot compaction (no atomics) + attention logits ----------
    // history: row r gets 2 warps (j = t in [0,64), valid j < L)
    bool hm_v = false; int hu_v = 0, hp = 0;
    {
        const int hw = (tid >> 5) & 1;   // warp within row
        int rt = 0;
        if (t < L) {
            long gi = (long)(b0 + r) * L + t;
            hm_v = mask_at(hist_m, gi, kind);
            hu_v = hist_u[gi];
            rt   = hist_r[gi];
        }
        unsigned bal = __ballot_sync(0xffffffffu, hm_v);
        hp = __popc(bal & ((1u << lane) - 1u));
        if (lane == 0) s_wcnt[r][hw] = __popc(bal);
        #pragma unroll
        for (int q = 0; q < NR; ++q) {
            unsigned bq = __ballot_sync(0xffffffffu, hm_v && (rt == q));
            if (lane == 0) s_rcnt2[r][hw][q] = __popc(bq);
        }
    }
    // social: 1 warp per row, S == 32 (complete compaction here)
    if (tid < R * S) {
        const int rr = tid >> 5;
        long gi = (long)(b0 + rr) * S + lane;
        bool m = mask_at(soc_m, gi, kind);
        int  u = soc_a[gi];
        unsigned bal = __ballot_sync(0xffffffffu, m);
        int p = __popc(bal & ((1u << lane) - 1u));
        if (m) s_su[rr][p] = u;
        if (lane == 0) s_sn[rr] = __popc(bal);
    }
    // attention: thread = (r, a = t>>2, dchunk = t&3)
    {
        const int a = t >> 2, dc = t & 3;
        float wg1r[16];
        {
            float4* wr = (float4*)wg1r;
            #pragma unroll
            for (int i = 0; i < 4; ++i)
                wr[i] = *(const float4*)&s_wg1T[a][dc * 16 + 4 * i];
        }
        const float bg1a = bg1[a];
        const float wg2a = wg2[a];
        #pragma unroll
        for (int g = 0; g < G; ++g) {
            float p = 0.f;
            #pragma unroll
            for (int i = 0; i < 4; ++i) {
                float4 mv = s_mem4[r][g][dc * 4 + i];
                p += mv.x * wg1r[4 * i]     + mv.y * wg1r[4 * i + 1]
                   + mv.z * wg1r[4 * i + 2] + mv.w * wg1r[4 * i + 3];
            }
            p += __shfl_xor_sync(0xffffffffu, p, 1);
            p += __shfl_xor_sync(0xffffffffu, p, 2);
            float lg = fast_tanh(p + bg1a) * wg2a;
            lg += __shfl_xor_sync(0xffffffffu, lg, 4);
            lg += __shfl_xor_sync(0xffffffffu, lg, 8);
            lg += __shfl_xor_sync(0xffffffffu, lg, 16);
            if (lane == 0)
                s_lg[(tid >> 5) & 1][r][g] = lg;
        }
    }
    __syncthreads();

    // ---------- P2b: hist scatter + softmax/self_feats -> g_comb ----------
    {
        const int hw = (tid >> 5) & 1;
        int base = hw ? s_wcnt[r][0] : 0;
        if (hm_v) s_hu[r][base + hp] = hu_v;
    }
    {
        const int d = t;
        const float bg2v = bg2[0];
        float lgv[G];
        #pragma unroll
        for (int g = 0; g < G; ++g)
            lgv[g] = s_lg[0][r][g] + s_lg[1][r][g] + bg2v;
        float mx = lgv[0];
        #pragma unroll
        for (int g = 1; g < G; ++g) mx = fmaxf(mx, lgv[g]);
        float sum = 0.f;
        #pragma unroll
        for (int g = 0; g < G; ++g) { lgv[g] = __expf(lgv[g] - mx); sum += lgv[g]; }
        const float inv = 1.f / sum;
        float sf = 0.f;
        #pragma unroll
        for (int g = 0; g < G; ++g)
            sf += lgv[g] * ((const float*)&s_mem4[r][g][0])[d];
        g_comb[(b0 + r) * (2 * D) + d] = sf * inv;
    }
    __syncthreads();

    // ---------- P3: gathers (thread = (r, e, d4)) ----------
    {
        const int e = t >> 4, d4 = t & 15;
        const float4* f4 = (const float4*)features;
        const int hn = s_wcnt[r][0] + s_wcnt[r][1];
        float4 ha = make_float4(0.f, 0.f, 0.f, 0.f);
        #pragma unroll 2
        for (int l = e; l < hn; l += 4) {
            int u = s_hu[r][l];
            float4 fv = f4[u * (D / 4) + d4];
            ha.x += fv.x; ha.y += fv.y; ha.z += fv.z; ha.w += fv.w;
        }
        s_red[e][r][d4] = ha;
        const int sn = s_sn[r];
        float4 sa = make_float4(0.f, 0.f, 0.f, 0.f);
        #pragma unroll 2
        for (int l = e; l < sn; l += 4) {
            int u = s_su[r][l];
            float4 fv = f4[u * (D / 4) + d4];
            sa.x += fv.x; sa.y += fv.y; sa.z += fv.z; sa.w += fv.w;
        }
        s_red[4 + e][r][d4] = sa;
    }
    __syncthreads();

    // ---------- P4: neighbor combine -> g_comb ----------
    {
        const int d = t;
        const float* rf = (const float*)s_red;
        float hs = 0.f, ss = 0.f;
        #pragma unroll
        for (int e = 0; e < 4; ++e) {
            hs += rf[((e)     * R + r) * D + d];
            ss += rf[((4 + e) * R + r) * D + d];
        }
        #pragma unroll
        for (int rt = 0; rt < NR; ++rt)
            hs += (float)(s_rcnt2[r][0][rt] + s_rcnt2[r][1][rt]) * r_embed[rt * D + d];
        const int hn = s_wcnt[r][0] + s_wcnt[r][1];
        float hmn = hs / fmaxf((float)hn, 1.f);
        float smn = ss / fmaxf((float)s_sn[r], 1.f);
        g_comb[(b0 + r) * (2 * D) + D + d] = 0.5f * (hmn + smn);
    }
}

// ---------------- kernel 2: out = relu(comb @ w1 + b1) ----------------
// comb: [B,128], w1: [128,64]. 32 rows per CTA, 256 threads.
constexpr int ROWS2 = 32;

__global__ __launch_bounds__(256)
void gemm_kernel(const float* __restrict__ w1,
                 const float* __restrict__ b1,
                 float* __restrict__ out)
{
    __shared__ __align__(16) float4 s_w1[2 * D][D / 4];     // 32 KB: w1[k][d4]
    __shared__ __align__(16) float4 s_c[ROWS2][(2 * D) / 4]; // 16 KB: comb[row][k4]

    const int tid  = threadIdx.x;
    const int row0 = blockIdx.x * ROWS2;

    const float4* w1v = (const float4*)w1;
    const float4* cv  = (const float4*)g_comb;

    for (int i = tid; i < 2 * D * (D / 4); i += 256)
        s_w1[i >> 4][i & 15] = w1v[i];
    for (int i = tid; i < ROWS2 * ((2 * D) / 4); i += 256) {
        int rr = i >> 5, k4 = i & 31;
        s_c[rr][k4] = cv[(row0 + rr) * 32 + k4];
    }
    __syncthreads();

    const int d4 = tid & 15;
    const int rq = tid >> 4;       // 0..15, rows {2rq, 2rq+1}
    float4 a0 = make_float4(0.f, 0.f, 0.f, 0.f);
    float4 a1 = make_float4(0.f, 0.f, 0.f, 0.f);

    #pragma unroll 8
    for (int kk = 0; kk < 32; ++kk) {
        float4 w0 = s_w1[4 * kk + 0][d4];
        float4 w1f = s_w1[4 * kk + 1][d4];
        float4 w2f = s_w1[4 * kk + 2][d4];
        float4 w3f = s_w1[4 * kk + 3][d4];
        float4 c0 = s_c[2 * rq][kk];
        float4 c1 = s_c[2 * rq + 1][kk];
        a0.x += c0.x * w0.x + c0.y * w1f.x + c0.z * w2f.x + c0.w * w3f.x;
        a0.y += c0.x * w0.y + c0.y * w1f.y + c0.z * w2f.y + c0.w * w3f.y;
        a0.z += c0.x * w0.z + c0.y * w1f.z + c0.z * w2f.z + c0.w * w3f.z;
        a0.w += c0.x * w0.w + c0.y * w1f.w + c0.z * w2f.w + c0.w * w3f.w;
        a1.x += c1.x * w0.x + c1.y * w1f.x + c1.z * w2f.x + c1.w * w3f.x;
        a1.y += c1.x * w0.y + c1.y * w1f.y + c1.z * w2f.y + c1.w * w3f.y;
        a1.z += c1.x * w0.z + c1.y * w1f.z + c1.z * w2f.z + c1.w * w3f.z;
        a1.w += c1.x * w0.w + c1.y * w1f.w + c1.z * w2f.w + c1.w * w3f.w;
    }

    float4 bv = ((const float4*)b1)[d4];
    float4* out4 = (float4*)out;
    float4 o0, o1;
    o0.x = fmaxf(a0.x + bv.x, 0.f); o0.y = fmaxf(a0.y + bv.y, 0.f);
    o0.z = fmaxf(a0.z + bv.z, 0.f); o0.w = fmaxf(a0.w + bv.w, 0.f);
    o1.x = fmaxf(a1.x + bv.x, 0.f); o1.y = fmaxf(a1.y + bv.y, 0.f);
    o1.z = fmaxf(a1.z + bv.z, 0.f); o1.w = fmaxf(a1.w + bv.w, 0.f);
    out4[(row0 + 2 * rq) * (D / 4) + d4]     = o0;
    out4[(row0 + 2 * rq + 1) * (D / 4) + d4] = o1;
}

} // namespace

extern "C" void kernel_launch(void* const* d_in, const int* in_sizes, int n_in,
                              void* d_out, int out_size)
{
    const int*   nodes    = (const int*)d_in[0];
    const int*   hist_u   = (const int*)d_in[1];
    const int*   hist_r   = (const int*)d_in[2];
    const void*  hist_m   = d_in[3];
    const int*   soc_a    = (const int*)d_in[4];
    const void*  soc_m    = d_in[5];
    const float* features = (const float*)d_in[6];
    const float* r_embed  = (const float*)d_in[7];
    const float* wg1      = (const float*)d_in[8];
    const float* bg1      = (const float*)d_in[9];
    const float* wg2      = (const float*)d_in[10];
    const float* bg2      = (const float*)d_in[11];
    const float* w1       = (const float*)d_in[12];
    const float* b1       = (const float*)d_in[13];
    float*       out      = (float*)d_out;

    const int B = in_sizes[0] / G;

    enc_kernel<<<B / R, NT>>>(nodes, hist_u, hist_r, hist_m, soc_a, soc_m,
                              features, r_embed, wg1, bg1, wg2, bg2);
    gemm_kernel<<<B / ROWS2, 256>>>(w1, b1, out);
}

// round 6
// speedup vs baseline: 1.0250x; 1.0250x over previous
#include <cuda_runtime.h>

namespace {

constexpr int G  = 8;    // group size
constexpr int L  = 50;   // history length
constexpr int S  = 32;   // social neighbors
constexpr int D  = 64;   // embed dim
constexpr int A  = 16;   // attention dim
constexpr int NR = 5;    // num ratings
constexpr int R  = 4;    // batch rows per CTA
constexpr int NT = 256;  // threads per CTA

__device__ __forceinline__ bool mask_at(const void* m, long idx, int kind)
{
    if (kind == 1) return ((const int*)m)[idx] != 0;
    if (kind == 2) return ((const float*)m)[idx] != 0.f;
    return ((const unsigned char*)m)[idx] != 0;
}

__device__ __forceinline__ float fast_tanh(float x)
{
    float y;
    asm("tanh.approx.f32 %0, %1;" : "=f"(y) : "f"(x));
    return y;
}

__global__ __launch_bounds__(NT, 6)
void enc_kernel(const int* __restrict__ nodes,
                const int* __restrict__ hist_u,
                const int* __restrict__ hist_r,
                const void* __restrict__ hist_m,
                const int* __restrict__ soc_a,
                const void* __restrict__ soc_m,
                const float* __restrict__ features,
                const float* __restrict__ r_embed,
                const float* __restrict__ wg1,
                const float* __restrict__ bg1,
                const float* __restrict__ wg2,
                const float* __restrict__ bg2,
                const float* __restrict__ w1,
                const float* __restrict__ b1,
                float* __restrict__ out)
{
    __shared__ __align__(16) float4 s_mem4[R][G][D / 4];   // member embeddings (8 KB)
    __shared__ __align__(16) float  s_wg1T[A][68];          // wg1 transposed, padded
    __shared__ __align__(16) float  s_comb[R][2 * D];       // [self | neigh] (2 KB)
    __shared__ __align__(16) float4 s_red[8][R][D / 4];     // reduction scratch (8 KB)
    __shared__ float s_lg[2][R][G];
    __shared__ int   s_hu[R][L];
    __shared__ int   s_su[R][S];
    __shared__ int   s_wcnt[R][2];        // hist per-warp counts
    __shared__ int   s_sn[R];
    __shared__ int   s_rcnt2[R][2][NR];   // per-warp rating histograms
    __shared__ int   s_flags[2];

    const int tid  = threadIdx.x;
    const int b0   = blockIdx.x * R;
    const int r    = tid >> 6;
    const int t    = tid & 63;
    const int lane = tid & 31;

    // ---------- P0 ----------
    if (tid < 2) s_flags[tid] = 0;
    __syncthreads();

    // ---------- P1: mask dtype detection + stage members + wg1T ----------
    if (tid < 64) {
        unsigned int v = ((const unsigned int*)hist_m)[tid];
        if (v > 1u)                      s_flags[0] = 1;   // benign race: only writes 1
        if (v != 0u && v != 0x3F800000u) s_flags[1] = 1;
    }
    for (int i = tid; i < R * G * (D / 4); i += NT) {
        int rr = i >> 7, g = (i >> 4) & 7, d4 = i & 15;
        int u = nodes[(b0 + rr) * G + g];
        s_mem4[rr][g][d4] = ((const float4*)features)[u * (D / 4) + d4];
    }
    for (int i = tid; i < D * A; i += NT) {
        int dd = i >> 4, a = i & 15;
        s_wg1T[a][dd] = wg1[i];
    }
    __syncthreads();

    const int kind = (!s_flags[0]) ? 1 : ((!s_flags[1]) ? 2 : 0);

    // ---------- P2a: ballot compaction (no atomics) + attention logits ----------
    // history: row r gets 2 warps (j = t in [0,64), valid j < L)
    bool hm_v = false; int hu_v = 0, hp = 0;
    {
        const int hw = (tid >> 5) & 1;   // warp within row
        int rt = 0;
        if (t < L) {
            long gi = (long)(b0 + r) * L + t;
            hm_v = mask_at(hist_m, gi, kind);
            hu_v = hist_u[gi];
            rt   = hist_r[gi];
        }
        unsigned bal = __ballot_sync(0xffffffffu, hm_v);
        hp = __popc(bal & ((1u << lane) - 1u));
        if (lane == 0) s_wcnt[r][hw] = __popc(bal);
        #pragma unroll
        for (int q = 0; q < NR; ++q) {
            unsigned bq = __ballot_sync(0xffffffffu, hm_v && (rt == q));
            if (lane == 0) s_rcnt2[r][hw][q] = __popc(bq);
        }
    }
    // social: 1 warp per row, S == 32 (complete compaction here)
    if (tid < R * S) {
        const int rr = tid >> 5;
        long gi = (long)(b0 + rr) * S + lane;
        bool m = mask_at(soc_m, gi, kind);
        int  u = soc_a[gi];
        unsigned bal = __ballot_sync(0xffffffffu, m);
        int p = __popc(bal & ((1u << lane) - 1u));
        if (m) s_su[rr][p] = u;
        if (lane == 0) s_sn[rr] = __popc(bal);
    }
    // attention: thread = (r, a = t>>2, dchunk = t&3)
    {
        const int a = t >> 2, dc = t & 3;
        float wg1r[16];
        {
            float4* wr = (float4*)wg1r;
            #pragma unroll
            for (int i = 0; i < 4; ++i)
                wr[i] = *(const float4*)&s_wg1T[a][dc * 16 + 4 * i];
        }
        const float bg1a = bg1[a];
        const float wg2a = wg2[a];
        #pragma unroll
        for (int g = 0; g < G; ++g) {
            float p = 0.f;
            #pragma unroll
            for (int i = 0; i < 4; ++i) {
                float4 mv = s_mem4[r][g][dc * 4 + i];
                p += mv.x * wg1r[4 * i]     + mv.y * wg1r[4 * i + 1]
                   + mv.z * wg1r[4 * i + 2] + mv.w * wg1r[4 * i + 3];
            }
            p += __shfl_xor_sync(0xffffffffu, p, 1);
            p += __shfl_xor_sync(0xffffffffu, p, 2);
            float lg = fast_tanh(p + bg1a) * wg2a;
            lg += __shfl_xor_sync(0xffffffffu, lg, 4);
            lg += __shfl_xor_sync(0xffffffffu, lg, 8);
            lg += __shfl_xor_sync(0xffffffffu, lg, 16);
            if (lane == 0)
                s_lg[(tid >> 5) & 1][r][g] = lg;
        }
    }
    __syncthreads();

    // ---------- P2b: hist scatter + softmax/self_feats ----------
    {
        const int hw = (tid >> 5) & 1;
        int base = hw ? s_wcnt[r][0] : 0;
        if (hm_v) s_hu[r][base + hp] = hu_v;
    }
    {
        const int d = t;
        const float bg2v = bg2[0];
        float lgv[G];
        #pragma unroll
        for (int g = 0; g < G; ++g)
            lgv[g] = s_lg[0][r][g] + s_lg[1][r][g] + bg2v;
        float mx = lgv[0];
        #pragma unroll
        for (int g = 1; g < G; ++g) mx = fmaxf(mx, lgv[g]);
        float sum = 0.f;
        #pragma unroll
        for (int g = 0; g < G; ++g) { lgv[g] = __expf(lgv[g] - mx); sum += lgv[g]; }
        const float inv = 1.f / sum;
        float sf = 0.f;
        #pragma unroll
        for (int g = 0; g < G; ++g)
            sf += lgv[g] * ((const float*)&s_mem4[r][g][0])[d];
        s_comb[r][d] = sf * inv;
    }
    __syncthreads();

    // ---------- P3: gathers (thread = (r, e, d4)) ----------
    {
        const int e = t >> 4, d4 = t & 15;
        const float4* f4 = (const float4*)features;
        const int hn = s_wcnt[r][0] + s_wcnt[r][1];
        float4 ha = make_float4(0.f, 0.f, 0.f, 0.f);
        #pragma unroll 2
        for (int l = e; l < hn; l += 4) {
            int u = s_hu[r][l];
            float4 fv = f4[u * (D / 4) + d4];
            ha.x += fv.x; ha.y += fv.y; ha.z += fv.z; ha.w += fv.w;
        }
        s_red[e][r][d4] = ha;
        const int sn = s_sn[r];
        float4 sa = make_float4(0.f, 0.f, 0.f, 0.f);
        #pragma unroll 2
        for (int l = e; l < sn; l += 4) {
            int u = s_su[r][l];
            float4 fv = f4[u * (D / 4) + d4];
            sa.x += fv.x; sa.y += fv.y; sa.z += fv.z; sa.w += fv.w;
        }
        s_red[4 + e][r][d4] = sa;
    }
    __syncthreads();

    // ---------- P4: neighbor combine ----------
    {
        const int d = t;
        const float* rf = (const float*)s_red;
        float hs = 0.f, ss = 0.f;
        #pragma unroll
        for (int e = 0; e < 4; ++e) {
            hs += rf[((e)     * R + r) * D + d];
            ss += rf[((4 + e) * R + r) * D + d];
        }
        #pragma unroll
        for (int rt = 0; rt < NR; ++rt)
            hs += (float)(s_rcnt2[r][0][rt] + s_rcnt2[r][1][rt]) * r_embed[rt * D + d];
        const int hn = s_wcnt[r][0] + s_wcnt[r][1];
        float hmn = hs / fmaxf((float)hn, 1.f);
        float smn = ss / fmaxf((float)s_sn[r], 1.f);
        s_comb[r][D + d] = 0.5f * (hmn + smn);
    }
    __syncthreads();

    // ---------- P5: final GEMM, k-split across 8 warps; half-warp = 2 rows ----------
    {
        const int w    = tid >> 5;           // k-slice: k in [16w, 16w+16)
        const int d4g  = lane & 15;
        const int rh   = lane >> 4;          // row-half: rows {2rh, 2rh+1}
        const float4* w1v = (const float4*)w1;
        float4 a0 = make_float4(0.f, 0.f, 0.f, 0.f);
        float4 a1 = make_float4(0.f, 0.f, 0.f, 0.f);
        #pragma unroll
        for (int i = 0; i < 16; ++i) {
            const int k = 16 * w + i;
            float4 wv = w1v[k * (D / 4) + d4g];
            float c0 = s_comb[2 * rh][k];
            float c1 = s_comb[2 * rh + 1][k];
            a0.x += c0 * wv.x; a0.y += c0 * wv.y; a0.z += c0 * wv.z; a0.w += c0 * wv.w;
            a1.x += c1 * wv.x; a1.y += c1 * wv.y; a1.z += c1 * wv.z; a1.w += c1 * wv.w;
        }
        s_red[w][2 * rh][d4g]     = a0;
        s_red[w][2 * rh + 1][d4g] = a1;
    }
    __syncthreads();

    // ---------- P6: reduce over 8 k-slices + bias + relu + store ----------
    {
        const int d = t;
        const float* rf = (const float*)s_red;
        float o = b1[d];
        #pragma unroll
        for (int w2 = 0; w2 < 8; ++w2)
            o += rf[(w2 * R + r) * D + d];
        out[(long)(b0 + r) * D + d] = fmaxf(o, 0.f);
    }
}

} // namespace

extern "C" void kernel_launch(void* const* d_in, const int* in_sizes, int n_in,
                              void* d_out, int out_size)
{
    const int*   nodes    = (const int*)d_in[0];
    const int*   hist_u   = (const int*)d_in[1];
    const int*   hist_r   = (const int*)d_in[2];
    const void*  hist_m   = d_in[3];
    const int*   soc_a    = (const int*)d_in[4];
    const void*  soc_m    = d_in[5];
    const float* features = (const float*)d_in[6];
    const float* r_embed  = (const float*)d_in[7];
    const float* wg1      = (const float*)d_in[8];
    const float* bg1      = (const float*)d_in[9];
    const float* wg2      = (const float*)d_in[10];
    const float* bg2      = (const float*)d_in[11];
    const float* w1       = (const float*)d_in[12];
    const float* b1       = (const float*)d_in[13];
    float*       out      = (float*)d_out;

    const int B = in_sizes[0] / G;

    enc_kernel<<<B / R, NT>>>(nodes, hist_u, hist_r, hist_m, soc_a, soc_m,
                              features, r_embed, wg1, bg1, wg2, bg2, w1, b1, out);
}

// round 7
// speedup vs baseline: 1.1445x; 1.1166x over previous
#include <cuda_runtime.h>

namespace {

constexpr int G  = 8;    // group size
constexpr int L  = 50;   // history length
constexpr int S  = 32;   // social neighbors
constexpr int D  = 64;   // embed dim
constexpr int A  = 16;   // attention dim
constexpr int NR = 5;    // num ratings
constexpr int R  = 4;    // batch rows per CTA
constexpr int NT = 256;  // threads per CTA

constexpr int UMAX = 100352;   // >= NUM_USERS, padded

// per-user attention logit: tanh(features[u] @ wg1 + bg1) @ wg2  (bg2 cancels in softmax)
__device__ float g_logit[UMAX];

__device__ __forceinline__ bool mask_at(const void* m, long idx, int kind)
{
    if (kind == 1) return ((const int*)m)[idx] != 0;
    if (kind == 2) return ((const float*)m)[idx] != 0.f;
    return ((const unsigned char*)m)[idx] != 0;
}

__device__ __forceinline__ float fast_tanh(float x)
{
    float y;
    asm("tanh.approx.f32 %0, %1;" : "=f"(y) : "f"(x));
    return y;
}

// ---------------- kernel A: per-user logit precompute ----------------
// CTA = 64 consecutive users, 256 threads: thread (u_local = tid>>2, q = tid&3)
// owns dims [16q, 16q+16) of its user's embedding.
constexpr int UPB = 64;

__global__ __launch_bounds__(256)
void logit_kernel(const float* __restrict__ features,
                  const float* __restrict__ wg1,
                  const float* __restrict__ bg1,
                  const float* __restrict__ wg2,
                  int n_users)
{
    __shared__ __align__(16) float4 s_f[UPB][D / 4];  // 16 KB
    __shared__ float s_w[D][A + 1];                    // wg1 padded
    __shared__ float s_b[A], s_v[A];

    const int tid = threadIdx.x;
    const int u0  = blockIdx.x * UPB;
    const int nv  = (n_users - u0 < UPB) ? (n_users - u0) : UPB;

    for (int i = tid; i < nv * (D / 4); i += 256)
        s_f[i >> 4][i & 15] = ((const float4*)features)[u0 * (D / 4) + i];
    for (int i = tid; i < D * A; i += 256)
        s_w[i >> 4][i & 15] = wg1[i];
    if (tid < A) { s_b[tid] = bg1[tid]; s_v[tid] = wg2[tid]; }
    __syncthreads();

    const int ul = tid >> 2;
    const int q  = tid & 3;
    if (ul >= nv) return;

    float mem[16];
    {
        float4* mp = (float4*)mem;
        #pragma unroll
        for (int i = 0; i < 4; ++i)
            mp[i] = s_f[ul][q * 4 + i];
    }

    float logit = 0.f;
    #pragma unroll
    for (int a = 0; a < A; ++a) {
        float acc = 0.f;
        #pragma unroll
        for (int i = 0; i < 16; ++i)
            acc += mem[i] * s_w[q * 16 + i][a];
        // reduce across the 4 q-lanes (lanes of one user are adjacent)
        acc += __shfl_xor_sync(0xffffffffu, acc, 1);
        acc += __shfl_xor_sync(0xffffffffu, acc, 2);
        logit += fast_tanh(acc + s_b[a]) * s_v[a];
    }
    if (q == 0) g_logit[u0 + ul] = logit;
}

// ---------------- kernel B: fused encoder ----------------
__global__ __launch_bounds__(NT, 6)
void enc_kernel(const int* __restrict__ nodes,
                const int* __restrict__ hist_u,
                const int* __restrict__ hist_r,
                const void* __restrict__ hist_m,
                const int* __restrict__ soc_a,
                const void* __restrict__ soc_m,
                const float* __restrict__ features,
                const float* __restrict__ r_embed,
                const float* __restrict__ w1,
                const float* __restrict__ b1,
                float* __restrict__ out)
{
    __shared__ __align__(16) float4 s_mem4[R][G][D / 4];   // member embeddings (8 KB)
    __shared__ __align__(16) float  s_comb[R][2 * D];       // [self | neigh] (2 KB)
    __shared__ __align__(16) float4 s_red[8][R][D / 4];     // reduction scratch (8 KB)
    __shared__ float s_lg[R][G];
    __shared__ int   s_hu[R][L];
    __shared__ int   s_su[R][S];
    __shared__ int   s_wcnt[R][2];        // hist per-warp counts
    __shared__ int   s_sn[R];
    __shared__ int   s_rcnt2[R][2][NR];   // per-warp rating histograms
    __shared__ int   s_flags[2];

    const int tid  = threadIdx.x;
    const int b0   = blockIdx.x * R;
    const int r    = tid >> 6;
    const int t    = tid & 63;
    const int lane = tid & 31;

    if (tid < 2) s_flags[tid] = 0;
    __syncthreads();

    // ---------- P1: mask dtype detect + stage members + member logits ----------
    if (tid < 64) {
        unsigned int v = ((const unsigned int*)hist_m)[tid];
        if (v > 1u)                      s_flags[0] = 1;   // benign race: only writes 1
        if (v != 0u && v != 0x3F800000u) s_flags[1] = 1;
    }
    for (int i = tid; i < R * G * (D / 4); i += NT) {
        int rr = i >> 7, g = (i >> 4) & 7, d4 = i & 15;
        int u = nodes[(b0 + rr) * G + g];
        s_mem4[rr][g][d4] = ((const float4*)features)[u * (D / 4) + d4];
    }
    if (tid >= 64 && tid < 64 + R * G) {
        int j  = tid - 64;
        int rr = j >> 3, g = j & 7;
        s_lg[rr][g] = g_logit[nodes[(b0 + rr) * G + g]];
    }
    __syncthreads();

    const int kind = (!s_flags[0]) ? 1 : ((!s_flags[1]) ? 2 : 0);

    // ---------- P2a: ballot compaction (no atomics) ----------
    bool hm_v = false; int hu_v = 0, hp = 0;
    {
        const int hw = (tid >> 5) & 1;   // warp within row
        int rt = 0;
        if (t < L) {
            long gi = (long)(b0 + r) * L + t;
            hm_v = mask_at(hist_m, gi, kind);
            hu_v = hist_u[gi];
            rt   = hist_r[gi];
        }
        unsigned bal = __ballot_sync(0xffffffffu, hm_v);
        hp = __popc(bal & ((1u << lane) - 1u));
        if (lane == 0) s_wcnt[r][hw] = __popc(bal);
        #pragma unroll
        for (int q = 0; q < NR; ++q) {
            unsigned bq = __ballot_sync(0xffffffffu, hm_v && (rt == q));
            if (lane == 0) s_rcnt2[r][hw][q] = __popc(bq);
        }
    }
    if (tid < R * S) {
        const int rr = tid >> 5;
        long gi = (long)(b0 + rr) * S + lane;
        bool m = mask_at(soc_m, gi, kind);
        int  u = soc_a[gi];
        unsigned bal = __ballot_sync(0xffffffffu, m);
        int p = __popc(bal & ((1u << lane) - 1u));
        if (m) s_su[rr][p] = u;
        if (lane == 0) s_sn[rr] = __popc(bal);
    }
    __syncthreads();

    // ---------- P2b: hist scatter + softmax/self_feats ----------
    {
        const int hw = (tid >> 5) & 1;
        int base = hw ? s_wcnt[r][0] : 0;
        if (hm_v) s_hu[r][base + hp] = hu_v;
    }
    {
        const int d = t;
        float lgv[G];
        #pragma unroll
        for (int g = 0; g < G; ++g)
            lgv[g] = s_lg[r][g];
        float mx = lgv[0];
        #pragma unroll
        for (int g = 1; g < G; ++g) mx = fmaxf(mx, lgv[g]);
        float sum = 0.f;
        #pragma unroll
        for (int g = 0; g < G; ++g) { lgv[g] = __expf(lgv[g] - mx); sum += lgv[g]; }
        const float inv = 1.f / sum;
        float sf = 0.f;
        #pragma unroll
        for (int g = 0; g < G; ++g)
            sf += lgv[g] * ((const float*)&s_mem4[r][g][0])[d];
        s_comb[r][d] = sf * inv;
    }
    __syncthreads();

    // ---------- P3: gathers (thread = (r, e, d4)) ----------
    {
        const int e = t >> 4, d4 = t & 15;
        const float4* f4 = (const float4*)features;
        const int hn = s_wcnt[r][0] + s_wcnt[r][1];
        float4 ha = make_float4(0.f, 0.f, 0.f, 0.f);
        #pragma unroll 2
        for (int l = e; l < hn; l += 4) {
            int u = s_hu[r][l];
            float4 fv = f4[u * (D / 4) + d4];
            ha.x += fv.x; ha.y += fv.y; ha.z += fv.z; ha.w += fv.w;
        }
        s_red[e][r][d4] = ha;
        const int sn = s_sn[r];
        float4 sa = make_float4(0.f, 0.f, 0.f, 0.f);
        #pragma unroll 2
        for (int l = e; l < sn; l += 4) {
            int u = s_su[r][l];
            float4 fv = f4[u * (D / 4) + d4];
            sa.x += fv.x; sa.y += fv.y; sa.z += fv.z; sa.w += fv.w;
        }
        s_red[4 + e][r][d4] = sa;
    }
    __syncthreads();

    // ---------- P4: neighbor combine ----------
    {
        const int d = t;
        const float* rf = (const float*)s_red;
        float hs = 0.f, ss = 0.f;
        #pragma unroll
        for (int e = 0; e < 4; ++e) {
            hs += rf[((e)     * R + r) * D + d];
            ss += rf[((4 + e) * R + r) * D + d];
        }
        #pragma unroll
        for (int rt = 0; rt < NR; ++rt)
            hs += (float)(s_rcnt2[r][0][rt] + s_rcnt2[r][1][rt]) * r_embed[rt * D + d];
        const int hn = s_wcnt[r][0] + s_wcnt[r][1];
        float hmn = hs / fmaxf((float)hn, 1.f);
        float smn = ss / fmaxf((float)s_sn[r], 1.f);
        s_comb[r][D + d] = 0.5f * (hmn + smn);
    }
    __syncthreads();

    // ---------- P5: final GEMM, k-split across 8 warps; half-warp = 2 rows ----------
    {
        const int w    = tid >> 5;           // k-slice: k in [16w, 16w+16)
        const int d4g  = lane & 15;
        const int rh   = lane >> 4;          // row-half: rows {2rh, 2rh+1}
        const float4* w1v = (const float4*)w1;
        float4 a0 = make_float4(0.f, 0.f, 0.f, 0.f);
        float4 a1 = make_float4(0.f, 0.f, 0.f, 0.f);
        #pragma unroll
        for (int j = 0; j < 4; ++j) {
            float c0a[4], c1a[4];
            *(float4*)c0a = *(const float4*)&s_comb[2 * rh][16 * w + 4 * j];
            *(float4*)c1a = *(const float4*)&s_comb[2 * rh + 1][16 * w + 4 * j];
            #pragma unroll
            for (int i = 0; i < 4; ++i) {
                const int k = 16 * w + 4 * j + i;
                float4 wv = w1v[k * (D / 4) + d4g];
                float c0 = c0a[i], c1 = c1a[i];
                a0.x += c0 * wv.x; a0.y += c0 * wv.y; a0.z += c0 * wv.z; a0.w += c0 * wv.w;
                a1.x += c1 * wv.x; a1.y += c1 * wv.y; a1.z += c1 * wv.z; a1.w += c1 * wv.w;
            }
        }
        s_red[w][2 * rh][d4g]     = a0;
        s_red[w][2 * rh + 1][d4g] = a1;
    }
    __syncthreads();

    // ---------- P6: reduce over 8 k-slices + bias + relu + store ----------
    {
        const int d = t;
        const float* rf = (const float*)s_red;
        float o = b1[d];
        #pragma unroll
        for (int w2 = 0; w2 < 8; ++w2)
            o += rf[(w2 * R + r) * D + d];
        out[(long)(b0 + r) * D + d] = fmaxf(o, 0.f);
    }
}

} // namespace

extern "C" void kernel_launch(void* const* d_in, const int* in_sizes, int n_in,
                              void* d_out, int out_size)
{
    const int*   nodes    = (const int*)d_in[0];
    const int*   hist_u   = (const int*)d_in[1];
    const int*   hist_r   = (const int*)d_in[2];
    const void*  hist_m   = d_in[3];
    const int*   soc_a    = (const int*)d_in[4];
    const void*  soc_m    = d_in[5];
    const float* features = (const float*)d_in[6];
    const float* r_embed  = (const float*)d_in[7];
    const float* wg1      = (const float*)d_in[8];
    const float* bg1      = (const float*)d_in[9];
    const float* wg2      = (const float*)d_in[10];
    // d_in[11] = bg2: cancels inside softmax, unused
    const float* w1       = (const float*)d_in[12];
    const float* b1       = (const float*)d_in[13];
    float*       out      = (float*)d_out;

    const int B       = in_sizes[0] / G;
    const int n_users = in_sizes[6] / D;

    logit_kernel<<<(n_users + UPB - 1) / UPB, 256>>>(features, wg1, bg1, wg2, n_users);
    enc_kernel<<<B / R, NT>>>(nodes, hist_u, hist_r, hist_m, soc_a, soc_m,
                              features, r_embed, w1, b1, out);
}

// round 8
// speedup vs baseline: 1.3800x; 1.2058x over previous
#include <cuda_runtime.h>

namespace {

constexpr int G  = 8;    // group size
constexpr int L  = 50;   // history length
constexpr int S  = 32;   // social neighbors
constexpr int D  = 64;   // embed dim
constexpr int A  = 16;   // attention dim
constexpr int NR = 5;    // num ratings
constexpr int R  = 4;    // batch rows per CTA
constexpr int NT = 256;  // threads per CTA

constexpr int UMAX = 100352;   // >= NUM_USERS, padded

// per-user attention logit: tanh(features[u] @ wg1 + bg1) @ wg2  (bg2 cancels in softmax)
__device__ float g_logit[UMAX];

__device__ __forceinline__ bool mask_at(const void* m, long idx, int kind)
{
    if (kind == 1) return ((const int*)m)[idx] != 0;
    if (kind == 2) return ((const float*)m)[idx] != 0.f;
    return ((const unsigned char*)m)[idx] != 0;
}

__device__ __forceinline__ float fast_tanh(float x)
{
    float y;
    asm("tanh.approx.f32 %0, %1;" : "=f"(y) : "f"(x));
    return y;
}

// ---------------- kernel A: per-user logit precompute ----------------
// CTA = 64 users, 256 threads: thread (ul = tid>>2, q = tid&3) owns dims
// [16q, 16q+16). Features read directly from GMEM (coalesced float4).
// wg1 staged transposed with q-padding for conflict-free LDS.128.
constexpr int UPB = 64;

__global__ __launch_bounds__(256)
void logit_kernel(const float* __restrict__ features,
                  const float* __restrict__ wg1,
                  const float* __restrict__ bg1,
                  const float* __restrict__ wg2,
                  int n_users)
{
    // s_w[a][q][i] = wg1[(16q + i)*A + a]; pad 16->24 floats so the 4 q-chunks
    // start at banks {0,24,16,8} (conflict-free LDS.128) and stay 16B-aligned.
    __shared__ __align__(16) float s_w[A][4][24];
    __shared__ float s_b[A], s_v[A];

    const int tid = threadIdx.x;
    const int u0  = blockIdx.x * UPB;

    for (int i = tid; i < D * A; i += 256) {
        int dd = i >> 4, a = i & 15;          // wg1[dd][a]
        s_w[a][dd >> 4][dd & 15] = wg1[i];
    }
    if (tid < A) { s_b[tid] = bg1[tid]; s_v[tid] = wg2[tid]; }
    __syncthreads();

    const int ul = tid >> 2;
    const int q  = tid & 3;
    const int u  = u0 + ul;

    float mem[16];
    {
        float4* mp = (float4*)mem;
        if (u < n_users) {
            const float4* f4 = (const float4*)features;
            #pragma unroll
            for (int i = 0; i < 4; ++i)
                mp[i] = f4[u * (D / 4) + q * 4 + i];   // consecutive lanes -> consecutive float4
        } else {
            #pragma unroll
            for (int i = 0; i < 4; ++i)
                mp[i] = make_float4(0.f, 0.f, 0.f, 0.f);
        }
    }

    float logit = 0.f;
    #pragma unroll
    for (int a = 0; a < A; ++a) {
        float wv[16];
        {
            float4* wp = (float4*)wv;
            #pragma unroll
            for (int i = 0; i < 4; ++i)
                wp[i] = *(const float4*)&s_w[a][q][4 * i];
        }
        float acc = 0.f;
        #pragma unroll
        for (int i = 0; i < 16; ++i)
            acc += mem[i] * wv[i];
        acc += __shfl_xor_sync(0xffffffffu, acc, 1);
        acc += __shfl_xor_sync(0xffffffffu, acc, 2);
        logit += fast_tanh(acc + s_b[a]) * s_v[a];
    }
    if (q == 0 && u < n_users)
        g_logit[u] = logit;
}

// ---------------- kernel B: fused encoder (unchanged from R7) ----------------
__global__ __launch_bounds__(NT, 6)
void enc_kernel(const int* __restrict__ nodes,
                const int* __restrict__ hist_u,
                const int* __restrict__ hist_r,
                const void* __restrict__ hist_m,
                const int* __restrict__ soc_a,
                const void* __restrict__ soc_m,
                const float* __restrict__ features,
                const float* __restrict__ r_embed,
                const float* __restrict__ w1,
                const float* __restrict__ b1,
                float* __restrict__ out)
{
    __shared__ __align__(16) float4 s_mem4[R][G][D / 4];   // member embeddings (8 KB)
    __shared__ __align__(16) float  s_comb[R][2 * D];       // [self | neigh] (2 KB)
    __shared__ __align__(16) float4 s_red[8][R][D / 4];     // reduction scratch (8 KB)
    __shared__ float s_lg[R][G];
    __shared__ int   s_hu[R][L];
    __shared__ int   s_su[R][S];
    __shared__ int   s_wcnt[R][2];        // hist per-warp counts
    __shared__ int   s_sn[R];
    __shared__ int   s_rcnt2[R][2][NR];   // per-warp rating histograms
    __shared__ int   s_flags[2];

    const int tid  = threadIdx.x;
    const int b0   = blockIdx.x * R;
    const int r    = tid >> 6;
    const int t    = tid & 63;
    const int lane = tid & 31;

    if (tid < 2) s_flags[tid] = 0;
    __syncthreads();

    // ---------- P1: mask dtype detect + stage members + member logits ----------
    if (tid < 64) {
        unsigned int v = ((const unsigned int*)hist_m)[tid];
        if (v > 1u)                      s_flags[0] = 1;   // benign race: only writes 1
        if (v != 0u && v != 0x3F800000u) s_flags[1] = 1;
    }
    for (int i = tid; i < R * G * (D / 4); i += NT) {
        int rr = i >> 7, g = (i >> 4) & 7, d4 = i & 15;
        int u = nodes[(b0 + rr) * G + g];
        s_mem4[rr][g][d4] = ((const float4*)features)[u * (D / 4) + d4];
    }
    if (tid >= 64 && tid < 64 + R * G) {
        int j  = tid - 64;
        int rr = j >> 3, g = j & 7;
        s_lg[rr][g] = g_logit[nodes[(b0 + rr) * G + g]];
    }
    __syncthreads();

    const int kind = (!s_flags[0]) ? 1 : ((!s_flags[1]) ? 2 : 0);

    // ---------- P2a: ballot compaction (no atomics) ----------
    bool hm_v = false; int hu_v = 0, hp = 0;
    {
        const int hw = (tid >> 5) & 1;   // warp within row
        int rt = 0;
        if (t < L) {
            long gi = (long)(b0 + r) * L + t;
            hm_v = mask_at(hist_m, gi, kind);
            hu_v = hist_u[gi];
            rt   = hist_r[gi];
        }
        unsigned bal = __ballot_sync(0xffffffffu, hm_v);
        hp = __popc(bal & ((1u << lane) - 1u));
        if (lane == 0) s_wcnt[r][hw] = __popc(bal);
        #pragma unroll
        for (int q = 0; q < NR; ++q) {
            unsigned bq = __ballot_sync(0xffffffffu, hm_v && (rt == q));
            if (lane == 0) s_rcnt2[r][hw][q] = __popc(bq);
        }
    }
    if (tid < R * S) {
        const int rr = tid >> 5;
        long gi = (long)(b0 + rr) * S + lane;
        bool m = mask_at(soc_m, gi, kind);
        int  u = soc_a[gi];
        unsigned bal = __ballot_sync(0xffffffffu, m);
        int p = __popc(bal & ((1u << lane) - 1u));
        if (m) s_su[rr][p] = u;
        if (lane == 0) s_sn[rr] = __popc(bal);
    }
    __syncthreads();

    // ---------- P2b: hist scatter + softmax/self_feats ----------
    {
        const int hw = (tid >> 5) & 1;
        int base = hw ? s_wcnt[r][0] : 0;
        if (hm_v) s_hu[r][base + hp] = hu_v;
    }
    {
        const int d = t;
        float lgv[G];
        #pragma unroll
        for (int g = 0; g < G; ++g)
            lgv[g] = s_lg[r][g];
        float mx = lgv[0];
        #pragma unroll
        for (int g = 1; g < G; ++g) mx = fmaxf(mx, lgv[g]);
        float sum = 0.f;
        #pragma unroll
        for (int g = 0; g < G; ++g) { lgv[g] = __expf(lgv[g] - mx); sum += lgv[g]; }
        const float inv = 1.f / sum;
        float sf = 0.f;
        #pragma unroll
        for (int g = 0; g < G; ++g)
            sf += lgv[g] * ((const float*)&s_mem4[r][g][0])[d];
        s_comb[r][d] = sf * inv;
    }
    __syncthreads();

    // ---------- P3: gathers (thread = (r, e, d4)) ----------
    {
        const int e = t >> 4, d4 = t & 15;
        const float4* f4 = (const float4*)features;
        const int hn = s_wcnt[r][0] + s_wcnt[r][1];
        float4 ha = make_float4(0.f, 0.f, 0.f, 0.f);
        #pragma unroll 2
        for (int l = e; l < hn; l += 4) {
            int u = s_hu[r][l];
            float4 fv = f4[u * (D / 4) + d4];
            ha.x += fv.x; ha.y += fv.y; ha.z += fv.z; ha.w += fv.w;
        }
        s_red[e][r][d4] = ha;
        const int sn = s_sn[r];
        float4 sa = make_float4(0.f, 0.f, 0.f, 0.f);
        #pragma unroll 2
        for (int l = e; l < sn; l += 4) {
            int u = s_su[r][l];
            float4 fv = f4[u * (D / 4) + d4];
            sa.x += fv.x; sa.y += fv.y; sa.z += fv.z; sa.w += fv.w;
        }
        s_red[4 + e][r][d4] = sa;
    }
    __syncthreads();

    // ---------- P4: neighbor combine ----------
    {
        const int d = t;
        const float* rf = (const float*)s_red;
        float hs = 0.f, ss = 0.f;
        #pragma unroll
        for (int e = 0; e < 4; ++e) {
            hs += rf[((e)     * R + r) * D + d];
            ss += rf[((4 + e) * R + r) * D + d];
        }
        #pragma unroll
        for (int rt = 0; rt < NR; ++rt)
            hs += (float)(s_rcnt2[r][0][rt] + s_rcnt2[r][1][rt]) * r_embed[rt * D + d];
        const int hn = s_wcnt[r][0] + s_wcnt[r][1];
        float hmn = hs / fmaxf((float)hn, 1.f);
        float smn = ss / fmaxf((float)s_sn[r], 1.f);
        s_comb[r][D + d] = 0.5f * (hmn + smn);
    }
    __syncthreads();

    // ---------- P5: final GEMM, k-split across 8 warps; half-warp = 2 rows ----------
    {
        const int w    = tid >> 5;           // k-slice: k in [16w, 16w+16)
        const int d4g  = lane & 15;
        const int rh   = lane >> 4;          // row-half: rows {2rh, 2rh+1}
        const float4* w1v = (const float4*)w1;
        float4 a0 = make_float4(0.f, 0.f, 0.f, 0.f);
        float4 a1 = make_float4(0.f, 0.f, 0.f, 0.f);
        #pragma unroll
        for (int j = 0; j < 4; ++j) {
            float c0a[4], c1a[4];
            *(float4*)c0a = *(const float4*)&s_comb[2 * rh][16 * w + 4 * j];
            *(float4*)c1a = *(const float4*)&s_comb[2 * rh + 1][16 * w + 4 * j];
            #pragma unroll
            for (int i = 0; i < 4; ++i) {
                const int k = 16 * w + 4 * j + i;
                float4 wv = w1v[k * (D / 4) + d4g];
                float c0 = c0a[i], c1 = c1a[i];
                a0.x += c0 * wv.x; a0.y += c0 * wv.y; a0.z += c0 * wv.z; a0.w += c0 * wv.w;
                a1.x += c1 * wv.x; a1.y += c1 * wv.y; a1.z += c1 * wv.z; a1.w += c1 * wv.w;
            }
        }
        s_red[w][2 * rh][d4g]     = a0;
        s_red[w][2 * rh + 1][d4g] = a1;
    }
    __syncthreads();

    // ---------- P6: reduce over 8 k-slices + bias + relu + store ----------
    {
        const int d = t;
        const float* rf = (const float*)s_red;
        float o = b1[d];
        #pragma unroll
        for (int w2 = 0; w2 < 8; ++w2)
            o += rf[(w2 * R + r) * D + d];
        out[(long)(b0 + r) * D + d] = fmaxf(o, 0.f);
    }
}

} // namespace

extern "C" void kernel_launch(void* const* d_in, const int* in_sizes, int n_in,
                              void* d_out, int out_size)
{
    const int*   nodes    = (const int*)d_in[0];
    const int*   hist_u   = (const int*)d_in[1];
    const int*   hist_r   = (const int*)d_in[2];
    const void*  hist_m   = d_in[3];
    const int*   soc_a    = (const int*)d_in[4];
    const void*  soc_m    = d_in[5];
    const float* features = (const float*)d_in[6];
    const float* r_embed  = (const float*)d_in[7];
    const float* wg1      = (const float*)d_in[8];
    const float* bg1      = (const float*)d_in[9];
    const float* wg2      = (const float*)d_in[10];
    // d_in[11] = bg2: cancels inside softmax, unused
    const float* w1       = (const float*)d_in[12];
    const float* b1       = (const float*)d_in[13];
    float*       out      = (float*)d_out;

    const int B       = in_sizes[0] / G;
    const int n_users = in_sizes[6] / D;

    logit_kernel<<<(n_users + UPB - 1) / UPB, 256>>>(features, wg1, bg1, wg2, n_users);
    enc_kernel<<<B / R, NT>>>(nodes, hist_u, hist_r, hist_m, soc_a, soc_m,
                              features, r_embed, w1, b1, out);
}